// round 2
// baseline (speedup 1.0000x reference)
#include <cuda_runtime.h>
#include <cstdint>

#define NN 50000
#define EE 850000
#define KH 4
#define DD 64
#define CC 256   // KH*DD

// ---------------- scratch ----------------
__device__ float g_h[(size_t)NN * CC];     // h[n][k*64+o], 1KB per node
__device__ float g_adst[NN * KH];          // alpha_dst[n][k]
__device__ float g_asrc[NN * KH];          // alpha_src[n][k]
__device__ int   g_cnt[NN];
__device__ int   g_off[NN + 1];
__device__ int   g_cur[NN];
__device__ int   g_csr[EE];
__device__ int   g_maxenc[KH];

__device__ __forceinline__ int enc_f(float f) {
    int b = __float_as_int(f);
    return b >= 0 ? b : (b ^ 0x7fffffff);
}
__device__ __forceinline__ float dec_f(int v) {
    return v >= 0 ? __int_as_float(v) : __int_as_float(v ^ 0x7fffffff);
}

// ---------------- K0: init ----------------
__global__ void k_init() {
    int t = blockIdx.x * blockDim.x + threadIdx.x;
    if (t < NN) g_cnt[t] = 0;
    if (t < KH) g_maxenc[t] = (int)0x80000000;
}

// ---------------- K1: fused GEMM h = x@W ([N,64]x[64,256]) + alpha dots ----------------
__global__ __launch_bounds__(256, 2) void k_gemm(const float* __restrict__ x,
                                                 const float* __restrict__ W,
                                                 const float* __restrict__ a) {
    extern __shared__ float sm[];
    float* Bs = sm;              // [64][256]  Bs[d*256+c] = W[k][d][o], c=k*64+o
    float* Xs = sm + 64 * 256;   // [64][68]   Xs[d*68+nl] = x[node0+nl][d]
    const int t = threadIdx.x;

    for (int idx = t; idx < 64 * 256; idx += 256) {
        int d = idx >> 8, c = idx & 255;
        Bs[idx] = W[(c >> 6) * 4096 + d * 64 + (c & 63)];
    }
    const int node0 = blockIdx.x * 64;
    for (int idx = t; idx < 4096; idx += 256) {
        int nl = idx >> 6, d = idx & 63;
        int n = node0 + nl;
        Xs[d * 68 + nl] = (n < NN) ? x[n * 64 + d] : 0.f;
    }
    __syncthreads();

    const int tx = t & 31, ty = t >> 5;
    const int c0 = tx * 8;

    float adc[8], asc[8];
#pragma unroll
    for (int j = 0; j < 8; j++) {
        int c = c0 + j, k = c >> 6, o = c & 63;
        adc[j] = a[k * 128 + o];
        asc[j] = a[k * 128 + 64 + o];
    }

    float acc[8][8];
#pragma unroll
    for (int i = 0; i < 8; i++)
#pragma unroll
        for (int j = 0; j < 8; j++) acc[i][j] = 0.f;

#pragma unroll 4
    for (int d = 0; d < 64; d++) {
        float4 b0 = *(const float4*)&Bs[d * 256 + c0];
        float4 b1 = *(const float4*)&Bs[d * 256 + c0 + 4];
        float4 xa = *(const float4*)&Xs[d * 68 + ty * 8];
        float4 xb = *(const float4*)&Xs[d * 68 + ty * 8 + 4];
        float xv[8] = {xa.x, xa.y, xa.z, xa.w, xb.x, xb.y, xb.z, xb.w};
        float bv[8] = {b0.x, b0.y, b0.z, b0.w, b1.x, b1.y, b1.z, b1.w};
#pragma unroll
        for (int i = 0; i < 8; i++)
#pragma unroll
            for (int j = 0; j < 8; j++) acc[i][j] += xv[i] * bv[j];
    }

#pragma unroll
    for (int i = 0; i < 8; i++) {
        int n = node0 + ty * 8 + i;
        float pd = 0.f, ps = 0.f;
#pragma unroll
        for (int j = 0; j < 8; j++) {
            pd += acc[i][j] * adc[j];
            ps += acc[i][j] * asc[j];
        }
#pragma unroll
        for (int off = 4; off; off >>= 1) {
            pd += __shfl_down_sync(0xffffffffu, pd, off, 8);
            ps += __shfl_down_sync(0xffffffffu, ps, off, 8);
        }
        if (n < NN) {
            float4* hp = (float4*)(g_h + (size_t)n * CC + c0);
            hp[0] = make_float4(acc[i][0], acc[i][1], acc[i][2], acc[i][3]);
            hp[1] = make_float4(acc[i][4], acc[i][5], acc[i][6], acc[i][7]);
            if ((tx & 7) == 0) {
                int k = tx >> 3;
                g_adst[n * 4 + k] = pd;
                g_asrc[n * 4 + k] = ps;
            }
        }
    }
}

// ---------------- K2: edge pass 1 — degree count + global per-head max ----------------
__global__ void k_pass1(const int* __restrict__ adj) {
    __shared__ int mk[KH];
    const int t = threadIdx.x;
    if (t < KH) mk[t] = (int)0x80000000;
    __syncthreads();

    int e = blockIdx.x * blockDim.x + t;
    float s0 = -1e30f, s1 = -1e30f, s2 = -1e30f, s3 = -1e30f;
    if (e < EE) {
        int dst = adj[e];
        int src = adj[EE + e];
        if ((unsigned)dst < NN && (unsigned)src < NN) {   // guard: survive dtype surprises
            atomicAdd(&g_cnt[dst], 1);
            float4 ad = *(const float4*)&g_adst[dst * 4];
            float4 as = *(const float4*)&g_asrc[src * 4];
            s0 = ad.x + as.x; s1 = ad.y + as.y; s2 = ad.z + as.z; s3 = ad.w + as.w;
        }
    }
#pragma unroll
    for (int off = 16; off; off >>= 1) {
        s0 = fmaxf(s0, __shfl_xor_sync(0xffffffffu, s0, off));
        s1 = fmaxf(s1, __shfl_xor_sync(0xffffffffu, s1, off));
        s2 = fmaxf(s2, __shfl_xor_sync(0xffffffffu, s2, off));
        s3 = fmaxf(s3, __shfl_xor_sync(0xffffffffu, s3, off));
    }
    if ((t & 31) == 0) {
        atomicMax(&mk[0], enc_f(s0));
        atomicMax(&mk[1], enc_f(s1));
        atomicMax(&mk[2], enc_f(s2));
        atomicMax(&mk[3], enc_f(s3));
    }
    __syncthreads();
    if (t < KH) atomicMax(&g_maxenc[t], mk[t]);
}

// ---------------- K3: single-block exclusive scan over degrees ----------------
__global__ void k_scan() {
    __shared__ int sd[1024];
    const int t = threadIdx.x;
    const int CH = (NN + 1023) / 1024;
    int s0 = t * CH;
    int e0 = s0 + CH; if (e0 > NN) e0 = NN;
    int s = 0;
    for (int i = s0; i < e0 && i < NN; i++) s += g_cnt[i];
    sd[t] = s;
    __syncthreads();
    for (int off = 1; off < 1024; off <<= 1) {
        int v = (t >= off) ? sd[t - off] : 0;
        __syncthreads();
        sd[t] += v;
        __syncthreads();
    }
    int pref = sd[t] - s;  // exclusive
    for (int i = s0; i < e0 && i < NN; i++) {
        g_off[i] = pref;
        g_cur[i] = pref;
        pref += g_cnt[i];
    }
}

// ---------------- K4: scatter edges into CSR buckets ----------------
__global__ void k_scatter(const int* __restrict__ adj) {
    int e = blockIdx.x * blockDim.x + threadIdx.x;
    if (e < EE) {
        int dst = adj[e];
        int src = adj[EE + e];
        if ((unsigned)dst < NN && (unsigned)src < NN) {
            int p = atomicAdd(&g_cur[dst], 1);
            if ((unsigned)p < EE) g_csr[p] = src;
        }
    }
}

// ---------------- K5: per-node gather + softmax aggregate + head mix + residual ----------------
// one warp per node; lane handles flat h columns [lane*8, lane*8+8), head = lane/8
__global__ __launch_bounds__(256) void k_gather(const float* __restrict__ x,
                                                const float* __restrict__ ew,
                                                float* __restrict__ out) {
    const int n = (blockIdx.x * blockDim.x + threadIdx.x) >> 5;
    const int lane = threadIdx.x & 31;
    if (n >= NN) return;
    const int k = lane >> 3;

    float M = dec_f(g_maxenc[k]);
    M = fmaxf(M, 0.01f * M);  // leaky_relu(max s) == max logits (monotone)
    const float ad = g_adst[n * 4 + k];
    const int beg = g_off[n];
    const int deg = g_cnt[n];

    float a0 = 0.f, a1 = 0.f, a2 = 0.f, a3 = 0.f, a4 = 0.f, a5 = 0.f, a6 = 0.f, a7 = 0.f;
    float den = 0.f;

    const float* hbase = g_h + lane * 8;
#pragma unroll 2
    for (int i = 0; i < deg; i++) {
        int src = g_csr[beg + i];
        float as = g_asrc[src * 4 + k];
        float s = ad + as;
        float l = fmaxf(s, 0.01f * s);
        float w = __expf(l - M);
        den += w;
        const float4* hp = (const float4*)(hbase + (size_t)src * CC);
        float4 h0 = hp[0];
        float4 h1 = hp[1];
        a0 += w * h0.x; a1 += w * h0.y; a2 += w * h0.z; a3 += w * h0.w;
        a4 += w * h1.x; a5 += w * h1.y; a6 += w * h1.z; a7 += w * h1.w;
    }

    const float sc = ew[n * 4 + k] / (den + 1e-8f);
    float v0 = a0 * sc, v1 = a1 * sc, v2 = a2 * sc, v3 = a3 * sc;
    float v4 = a4 * sc, v5 = a5 * sc, v6 = a6 * sc, v7 = a7 * sc;

#pragma unroll
    for (int off = 8; off <= 16; off <<= 1) {
        v0 += __shfl_xor_sync(0xffffffffu, v0, off);
        v1 += __shfl_xor_sync(0xffffffffu, v1, off);
        v2 += __shfl_xor_sync(0xffffffffu, v2, off);
        v3 += __shfl_xor_sync(0xffffffffu, v3, off);
        v4 += __shfl_xor_sync(0xffffffffu, v4, off);
        v5 += __shfl_xor_sync(0xffffffffu, v5, off);
        v6 += __shfl_xor_sync(0xffffffffu, v6, off);
        v7 += __shfl_xor_sync(0xffffffffu, v7, off);
    }

    if (lane < 8) {
        const float4* xp = (const float4*)(x + n * 64 + lane * 8);
        float4 x0 = xp[0];
        float4 x1 = xp[1];
        float4* op = (float4*)(out + n * 64 + lane * 8);
        op[0] = make_float4(v0 + x0.x, v1 + x0.y, v2 + x0.z, v3 + x0.w);
        op[1] = make_float4(v4 + x1.x, v5 + x1.y, v6 + x1.z, v7 + x1.w);
    }
}

// ---------------- launch ----------------
extern "C" void kernel_launch(void* const* d_in, const int* in_sizes, int n_in,
                              void* d_out, int out_size) {
    const float* x   = (const float*)d_in[0];
    const int*   adj = (const int*)d_in[1];
    const float* ew  = (const float*)d_in[2];
    const float* W   = (const float*)d_in[3];
    const float* a   = (const float*)d_in[4];
    float*       out = (float*)d_out;

    const size_t smem = (64 * 256 + 64 * 68) * sizeof(float);  // 82944 B
    static bool attr_set = false;
    if (!attr_set) {
        cudaFuncSetAttribute(k_gemm, cudaFuncAttributeMaxDynamicSharedMemorySize, (int)smem);
        attr_set = true;
    }

    k_init<<<(NN + 255) / 256, 256>>>();
    k_gemm<<<(NN + 63) / 64, 256, smem>>>(x, W, a);
    k_pass1<<<(EE + 255) / 256, 256>>>(adj);
    k_scan<<<1, 1024>>>();
    k_scatter<<<(EE + 255) / 256, 256>>>(adj);
    k_gather<<<(NN * 32 + 255) / 256, 256>>>(x, ew, out);
}

// round 3
// speedup vs baseline: 2.1986x; 2.1986x over previous
#include <cuda_runtime.h>
#include <cstdint>

#define NN 50000
#define EE 850000
#define KH 4
#define DD 64
#define CC 256   // KH*DD

// ---------------- scratch ----------------
__device__ float g_h[(size_t)NN * CC];     // h[n][k*64+o], 1KB per node
__device__ float g_adst[NN * KH];          // alpha_dst[n][k]
__device__ float g_asrc[NN * KH];          // alpha_src[n][k]
__device__ int   g_cnt[NN];
__device__ int   g_off[NN + 1];
__device__ int   g_cur[NN];
__device__ int   g_csr[EE];
__device__ int   g_maxenc[KH];
__device__ int   g_total;

__device__ __forceinline__ int enc_f(float f) {
    int b = __float_as_int(f);
    return b >= 0 ? b : (b ^ 0x7fffffff);
}
__device__ __forceinline__ float dec_f(int v) {
    return v >= 0 ? __int_as_float(v) : __int_as_float(v ^ 0x7fffffff);
}

// ---------------- K0: init ----------------
__global__ void k_init() {
    int t = blockIdx.x * blockDim.x + threadIdx.x;
    if (t < NN) g_cnt[t] = 0;
    if (t < KH) g_maxenc[t] = (int)0x80000000;
    if (t == KH) g_total = 0;
}

// ---------------- K1: fused GEMM h = x@W ([N,64]x[64,256]) + alpha dots ----------------
__global__ __launch_bounds__(256, 2) void k_gemm(const float* __restrict__ x,
                                                 const float* __restrict__ W,
                                                 const float* __restrict__ a) {
    extern __shared__ float sm[];
    float* Bs = sm;              // [64][256]  Bs[d*256+c] = W[k][d][o], c=k*64+o
    float* Xs = sm + 64 * 256;   // [64][68]   Xs[d*68+nl] = x[node0+nl][d]
    const int t = threadIdx.x;

    for (int idx = t; idx < 64 * 256; idx += 256) {
        int d = idx >> 8, c = idx & 255;
        Bs[idx] = W[(c >> 6) * 4096 + d * 64 + (c & 63)];
    }
    const int node0 = blockIdx.x * 64;
    for (int idx = t; idx < 4096; idx += 256) {
        int nl = idx >> 6, d = idx & 63;
        int n = node0 + nl;
        Xs[d * 68 + nl] = (n < NN) ? x[n * 64 + d] : 0.f;
    }
    __syncthreads();

    const int tx = t & 31, ty = t >> 5;
    const int c0 = tx * 8;

    float adc[8], asc[8];
#pragma unroll
    for (int j = 0; j < 8; j++) {
        int c = c0 + j, k = c >> 6, o = c & 63;
        adc[j] = a[k * 128 + o];
        asc[j] = a[k * 128 + 64 + o];
    }

    float acc[8][8];
#pragma unroll
    for (int i = 0; i < 8; i++)
#pragma unroll
        for (int j = 0; j < 8; j++) acc[i][j] = 0.f;

#pragma unroll 4
    for (int d = 0; d < 64; d++) {
        float4 b0 = *(const float4*)&Bs[d * 256 + c0];
        float4 b1 = *(const float4*)&Bs[d * 256 + c0 + 4];
        float4 xa = *(const float4*)&Xs[d * 68 + ty * 8];
        float4 xb = *(const float4*)&Xs[d * 68 + ty * 8 + 4];
        float xv[8] = {xa.x, xa.y, xa.z, xa.w, xb.x, xb.y, xb.z, xb.w};
        float bv[8] = {b0.x, b0.y, b0.z, b0.w, b1.x, b1.y, b1.z, b1.w};
#pragma unroll
        for (int i = 0; i < 8; i++)
#pragma unroll
            for (int j = 0; j < 8; j++) acc[i][j] += xv[i] * bv[j];
    }

#pragma unroll
    for (int i = 0; i < 8; i++) {
        int n = node0 + ty * 8 + i;
        float pd = 0.f, ps = 0.f;
#pragma unroll
        for (int j = 0; j < 8; j++) {
            pd += acc[i][j] * adc[j];
            ps += acc[i][j] * asc[j];
        }
#pragma unroll
        for (int off = 4; off; off >>= 1) {
            pd += __shfl_down_sync(0xffffffffu, pd, off, 8);
            ps += __shfl_down_sync(0xffffffffu, ps, off, 8);
        }
        if (n < NN) {
            float4* hp = (float4*)(g_h + (size_t)n * CC + c0);
            hp[0] = make_float4(acc[i][0], acc[i][1], acc[i][2], acc[i][3]);
            hp[1] = make_float4(acc[i][4], acc[i][5], acc[i][6], acc[i][7]);
            if ((tx & 7) == 0) {
                int k = tx >> 3;
                g_adst[n * 4 + k] = pd;
                g_asrc[n * 4 + k] = ps;
            }
        }
    }
}

// ---------------- K2: edge pass 1 — degree count + global per-head max ----------------
__global__ void k_pass1(const int* __restrict__ adj) {
    __shared__ int mk[KH];
    const int t = threadIdx.x;
    if (t < KH) mk[t] = (int)0x80000000;
    __syncthreads();

    int e = blockIdx.x * blockDim.x + t;
    float s0 = -1e30f, s1 = -1e30f, s2 = -1e30f, s3 = -1e30f;
    if (e < EE) {
        int dst = adj[e];
        int src = adj[EE + e];
        if ((unsigned)dst < NN && (unsigned)src < NN) {
            atomicAdd(&g_cnt[dst], 1);
            float4 ad = *(const float4*)&g_adst[dst * 4];
            float4 as = *(const float4*)&g_asrc[src * 4];
            s0 = ad.x + as.x; s1 = ad.y + as.y; s2 = ad.z + as.z; s3 = ad.w + as.w;
        }
    }
#pragma unroll
    for (int off = 16; off; off >>= 1) {
        s0 = fmaxf(s0, __shfl_xor_sync(0xffffffffu, s0, off));
        s1 = fmaxf(s1, __shfl_xor_sync(0xffffffffu, s1, off));
        s2 = fmaxf(s2, __shfl_xor_sync(0xffffffffu, s2, off));
        s3 = fmaxf(s3, __shfl_xor_sync(0xffffffffu, s3, off));
    }
    if ((t & 31) == 0) {
        atomicMax(&mk[0], enc_f(s0));
        atomicMax(&mk[1], enc_f(s1));
        atomicMax(&mk[2], enc_f(s2));
        atomicMax(&mk[3], enc_f(s3));
    }
    __syncthreads();
    if (t < KH) atomicMax(&g_maxenc[t], mk[t]);
}

// ---------------- K3: parallel bucket allocation (order-free "scan") ----------------
// Buckets need only be contiguous per node, NOT ordered by node id. Warp-scan
// the 32 counts, one atomicAdd per warp on a global cursor, broadcast base.
__global__ void k_alloc() {
    const int n = blockIdx.x * blockDim.x + threadIdx.x;
    const int lane = threadIdx.x & 31;
    int c = (n < NN) ? g_cnt[n] : 0;

    // inclusive warp scan
    int incl = c;
#pragma unroll
    for (int off = 1; off < 32; off <<= 1) {
        int v = __shfl_up_sync(0xffffffffu, incl, off);
        if (lane >= off) incl += v;
    }
    int wtotal = __shfl_sync(0xffffffffu, incl, 31);
    int base = 0;
    if (lane == 31) base = atomicAdd(&g_total, wtotal);
    base = __shfl_sync(0xffffffffu, base, 31);

    if (n < NN) {
        int off = base + incl - c;   // exclusive within warp
        g_off[n] = off;
        g_cur[n] = off;
    }
}

// ---------------- K4: scatter edges into CSR buckets ----------------
__global__ void k_scatter(const int* __restrict__ adj) {
    int e = blockIdx.x * blockDim.x + threadIdx.x;
    if (e < EE) {
        int dst = adj[e];
        int src = adj[EE + e];
        if ((unsigned)dst < NN && (unsigned)src < NN) {
            int p = atomicAdd(&g_cur[dst], 1);
            if ((unsigned)p < EE) g_csr[p] = src;
        }
    }
}

// ---------------- K5: per-node gather + softmax aggregate + head mix + residual ----------------
__global__ __launch_bounds__(256) void k_gather(const float* __restrict__ x,
                                                const float* __restrict__ ew,
                                                float* __restrict__ out) {
    const int n = (blockIdx.x * blockDim.x + threadIdx.x) >> 5;
    const int lane = threadIdx.x & 31;
    if (n >= NN) return;
    const int k = lane >> 3;

    float M = dec_f(g_maxenc[k]);
    M = fmaxf(M, 0.01f * M);  // leaky_relu(max s) == max logits (monotone)
    const float ad = g_adst[n * 4 + k];
    const int beg = g_off[n];
    const int deg = g_cnt[n];

    float a0 = 0.f, a1 = 0.f, a2 = 0.f, a3 = 0.f, a4 = 0.f, a5 = 0.f, a6 = 0.f, a7 = 0.f;
    float den = 0.f;

    const float* hbase = g_h + lane * 8;
#pragma unroll 2
    for (int i = 0; i < deg; i++) {
        int src = g_csr[beg + i];
        float as = g_asrc[src * 4 + k];
        float s = ad + as;
        float l = fmaxf(s, 0.01f * s);
        float w = __expf(l - M);
        den += w;
        const float4* hp = (const float4*)(hbase + (size_t)src * CC);
        float4 h0 = hp[0];
        float4 h1 = hp[1];
        a0 += w * h0.x; a1 += w * h0.y; a2 += w * h0.z; a3 += w * h0.w;
        a4 += w * h1.x; a5 += w * h1.y; a6 += w * h1.z; a7 += w * h1.w;
    }

    const float sc = ew[n * 4 + k] / (den + 1e-8f);
    float v0 = a0 * sc, v1 = a1 * sc, v2 = a2 * sc, v3 = a3 * sc;
    float v4 = a4 * sc, v5 = a5 * sc, v6 = a6 * sc, v7 = a7 * sc;

#pragma unroll
    for (int off = 8; off <= 16; off <<= 1) {
        v0 += __shfl_xor_sync(0xffffffffu, v0, off);
        v1 += __shfl_xor_sync(0xffffffffu, v1, off);
        v2 += __shfl_xor_sync(0xffffffffu, v2, off);
        v3 += __shfl_xor_sync(0xffffffffu, v3, off);
        v4 += __shfl_xor_sync(0xffffffffu, v4, off);
        v5 += __shfl_xor_sync(0xffffffffu, v5, off);
        v6 += __shfl_xor_sync(0xffffffffu, v6, off);
        v7 += __shfl_xor_sync(0xffffffffu, v7, off);
    }

    if (lane < 8) {
        const float4* xp = (const float4*)(x + n * 64 + lane * 8);
        float4 x0 = xp[0];
        float4 x1 = xp[1];
        float4* op = (float4*)(out + n * 64 + lane * 8);
        op[0] = make_float4(v0 + x0.x, v1 + x0.y, v2 + x0.z, v3 + x0.w);
        op[1] = make_float4(v4 + x1.x, v5 + x1.y, v6 + x1.z, v7 + x1.w);
    }
}

// ---------------- launch ----------------
extern "C" void kernel_launch(void* const* d_in, const int* in_sizes, int n_in,
                              void* d_out, int out_size) {
    const float* x   = (const float*)d_in[0];
    const int*   adj = (const int*)d_in[1];
    const float* ew  = (const float*)d_in[2];
    const float* W   = (const float*)d_in[3];
    const float* a   = (const float*)d_in[4];
    float*       out = (float*)d_out;

    const size_t smem = (64 * 256 + 64 * 68) * sizeof(float);  // 82944 B
    static bool attr_set = false;
    if (!attr_set) {
        cudaFuncSetAttribute(k_gemm, cudaFuncAttributeMaxDynamicSharedMemorySize, (int)smem);
        attr_set = true;
    }

    k_init<<<(NN + 255) / 256, 256>>>();
    k_gemm<<<(NN + 63) / 64, 256, smem>>>(x, W, a);
    k_pass1<<<(EE + 255) / 256, 256>>>(adj);
    k_alloc<<<(NN + 255) / 256, 256>>>();
    k_scatter<<<(EE + 255) / 256, 256>>>(adj);
    k_gather<<<(NN * 32 + 255) / 256, 256>>>(x, ew, out);
}

// round 4
// speedup vs baseline: 2.9150x; 1.3258x over previous
#include <cuda_runtime.h>
#include <cuda_bf16.h>
#include <cstdint>

#define NN 50000
#define EE 850000
#define KH 4
#define DD 64
#define CC 256   // KH*DD

// ---------------- scratch ----------------
__device__ __nv_bfloat16 g_hb[(size_t)NN * CC];  // h[n][k*64+o] bf16, 512B/node
__device__ float g_adst[NN * KH];
__device__ float g_asrc[NN * KH];
__device__ int   g_cnt[NN];
__device__ int   g_off[NN];
__device__ int   g_cur[NN];
__device__ int   g_csr[EE];
__device__ int   g_maxenc[KH];
__device__ int   g_total;

__device__ __forceinline__ int enc_f(float f) {
    int b = __float_as_int(f);
    return b >= 0 ? b : (b ^ 0x7fffffff);
}
__device__ __forceinline__ float dec_f(int v) {
    return v >= 0 ? __int_as_float(v) : __int_as_float(v ^ 0x7fffffff);
}

// ---------------- K0: init ----------------
__global__ void k_init() {
    int t = blockIdx.x * blockDim.x + threadIdx.x;
    if (t < NN) g_cnt[t] = 0;
    if (t < KH) g_maxenc[t] = (int)0x80000000;
    if (t == KH) g_total = 0;
}

// ---------------- K1: fused GEMM h = x@W ([N,64]x[64,256]) + alpha dots, bf16 h out ----
__global__ __launch_bounds__(256, 2) void k_gemm(const float* __restrict__ x,
                                                 const float* __restrict__ W,
                                                 const float* __restrict__ a) {
    extern __shared__ float sm[];
    float* Bs = sm;              // [64][256]
    float* Xs = sm + 64 * 256;   // [64][68]
    const int t = threadIdx.x;

    for (int idx = t; idx < 64 * 256; idx += 256) {
        int d = idx >> 8, c = idx & 255;
        Bs[idx] = W[(c >> 6) * 4096 + d * 64 + (c & 63)];
    }
    const int node0 = blockIdx.x * 64;
    for (int idx = t; idx < 4096; idx += 256) {
        int nl = idx >> 6, d = idx & 63;
        int n = node0 + nl;
        Xs[d * 68 + nl] = (n < NN) ? x[n * 64 + d] : 0.f;
    }
    __syncthreads();

    const int tx = t & 31, ty = t >> 5;
    const int c0 = tx * 8;

    float adc[8], asc[8];
#pragma unroll
    for (int j = 0; j < 8; j++) {
        int c = c0 + j, k = c >> 6, o = c & 63;
        adc[j] = a[k * 128 + o];
        asc[j] = a[k * 128 + 64 + o];
    }

    float acc[8][8];
#pragma unroll
    for (int i = 0; i < 8; i++)
#pragma unroll
        for (int j = 0; j < 8; j++) acc[i][j] = 0.f;

#pragma unroll 4
    for (int d = 0; d < 64; d++) {
        float4 b0 = *(const float4*)&Bs[d * 256 + c0];
        float4 b1 = *(const float4*)&Bs[d * 256 + c0 + 4];
        float4 xa = *(const float4*)&Xs[d * 68 + ty * 8];
        float4 xb = *(const float4*)&Xs[d * 68 + ty * 8 + 4];
        float xv[8] = {xa.x, xa.y, xa.z, xa.w, xb.x, xb.y, xb.z, xb.w};
        float bv[8] = {b0.x, b0.y, b0.z, b0.w, b1.x, b1.y, b1.z, b1.w};
#pragma unroll
        for (int i = 0; i < 8; i++)
#pragma unroll
            for (int j = 0; j < 8; j++) acc[i][j] += xv[i] * bv[j];
    }

#pragma unroll
    for (int i = 0; i < 8; i++) {
        int n = node0 + ty * 8 + i;
        float pd = 0.f, ps = 0.f;
#pragma unroll
        for (int j = 0; j < 8; j++) {
            pd += acc[i][j] * adc[j];
            ps += acc[i][j] * asc[j];
        }
#pragma unroll
        for (int off = 4; off; off >>= 1) {
            pd += __shfl_down_sync(0xffffffffu, pd, off, 8);
            ps += __shfl_down_sync(0xffffffffu, ps, off, 8);
        }
        if (n < NN) {
            __nv_bfloat162 p0 = __floats2bfloat162_rn(acc[i][0], acc[i][1]);
            __nv_bfloat162 p1 = __floats2bfloat162_rn(acc[i][2], acc[i][3]);
            __nv_bfloat162 p2 = __floats2bfloat162_rn(acc[i][4], acc[i][5]);
            __nv_bfloat162 p3 = __floats2bfloat162_rn(acc[i][6], acc[i][7]);
            uint4 pk;
            pk.x = *(unsigned*)&p0; pk.y = *(unsigned*)&p1;
            pk.z = *(unsigned*)&p2; pk.w = *(unsigned*)&p3;
            *(uint4*)(g_hb + (size_t)n * CC + c0) = pk;
            if ((tx & 7) == 0) {
                int k = tx >> 3;
                g_adst[n * 4 + k] = pd;
                g_asrc[n * 4 + k] = ps;
            }
        }
    }
}

// ---------------- K2a: degree count (independent of GEMM — side stream) --------------
__global__ void k_cnt(const int* __restrict__ adj) {
    int e = blockIdx.x * blockDim.x + threadIdx.x;
    if (e < EE) {
        int dst = adj[e];
        if ((unsigned)dst < NN) atomicAdd(&g_cnt[dst], 1);
    }
}

// ---------------- K2b: parallel bucket allocation (order-free) ----------------
__global__ void k_alloc() {
    const int n = blockIdx.x * blockDim.x + threadIdx.x;
    const int lane = threadIdx.x & 31;
    int c = (n < NN) ? g_cnt[n] : 0;

    int incl = c;
#pragma unroll
    for (int off = 1; off < 32; off <<= 1) {
        int v = __shfl_up_sync(0xffffffffu, incl, off);
        if (lane >= off) incl += v;
    }
    int wtotal = __shfl_sync(0xffffffffu, incl, 31);
    int base = 0;
    if (lane == 31) base = atomicAdd(&g_total, wtotal);
    base = __shfl_sync(0xffffffffu, base, 31);

    if (n < NN) {
        int off = base + incl - c;
        g_off[n] = off;
        g_cur[n] = off;
    }
}

// ---------------- K2c: scatter edges into CSR buckets (side stream) ----------------
__global__ void k_scatter(const int* __restrict__ adj) {
    int e = blockIdx.x * blockDim.x + threadIdx.x;
    if (e < EE) {
        int dst = adj[e];
        int src = adj[EE + e];
        if ((unsigned)dst < NN && (unsigned)src < NN) {
            int p = atomicAdd(&g_cur[dst], 1);
            if ((unsigned)p < EE) g_csr[p] = src;
        }
    }
}

// ---------------- K3: global per-head max over edges (after GEMM) ----------------
__global__ void k_max(const int* __restrict__ adj) {
    __shared__ int mk[KH];
    const int t = threadIdx.x;
    if (t < KH) mk[t] = (int)0x80000000;
    __syncthreads();

    int e = blockIdx.x * blockDim.x + t;
    float s0 = -1e30f, s1 = -1e30f, s2 = -1e30f, s3 = -1e30f;
    if (e < EE) {
        int dst = adj[e];
        int src = adj[EE + e];
        if ((unsigned)dst < NN && (unsigned)src < NN) {
            float4 ad = *(const float4*)&g_adst[dst * 4];
            float4 as = *(const float4*)&g_asrc[src * 4];
            s0 = ad.x + as.x; s1 = ad.y + as.y; s2 = ad.z + as.z; s3 = ad.w + as.w;
        }
    }
#pragma unroll
    for (int off = 16; off; off >>= 1) {
        s0 = fmaxf(s0, __shfl_xor_sync(0xffffffffu, s0, off));
        s1 = fmaxf(s1, __shfl_xor_sync(0xffffffffu, s1, off));
        s2 = fmaxf(s2, __shfl_xor_sync(0xffffffffu, s2, off));
        s3 = fmaxf(s3, __shfl_xor_sync(0xffffffffu, s3, off));
    }
    if ((t & 31) == 0) {
        atomicMax(&mk[0], enc_f(s0));
        atomicMax(&mk[1], enc_f(s1));
        atomicMax(&mk[2], enc_f(s2));
        atomicMax(&mk[3], enc_f(s3));
    }
    __syncthreads();
    if (t < KH) atomicMax(&g_maxenc[t], mk[t]);
}

// ---------------- K4: per-node gather + softmax aggregate + head mix + residual ------
// one warp per node; lane handles flat h columns [lane*8, lane*8+8), head = lane/8
__global__ __launch_bounds__(256) void k_gather(const float* __restrict__ x,
                                                const float* __restrict__ ew,
                                                float* __restrict__ out) {
    const int n = (blockIdx.x * blockDim.x + threadIdx.x) >> 5;
    const int lane = threadIdx.x & 31;
    if (n >= NN) return;
    const int k = lane >> 3;

    float M = dec_f(g_maxenc[k]);
    M = fmaxf(M, 0.01f * M);  // leaky_relu(max s) == max logits (monotone)
    const float ad = g_adst[n * 4 + k];
    const int beg = g_off[n];
    const int deg = g_cnt[n];

    float a0 = 0.f, a1 = 0.f, a2 = 0.f, a3 = 0.f, a4 = 0.f, a5 = 0.f, a6 = 0.f, a7 = 0.f;
    float den = 0.f;

    const __nv_bfloat16* hbase = g_hb + lane * 8;
#pragma unroll 2
    for (int i = 0; i < deg; i++) {
        int src = g_csr[beg + i];
        float as = g_asrc[src * 4 + k];
        float s = ad + as;
        float l = fmaxf(s, 0.01f * s);
        float w = __expf(l - M);
        den += w;
        uint4 raw = *(const uint4*)(hbase + (size_t)src * CC);
        float2 f0 = __bfloat1622float2(*(__nv_bfloat162*)&raw.x);
        float2 f1 = __bfloat1622float2(*(__nv_bfloat162*)&raw.y);
        float2 f2 = __bfloat1622float2(*(__nv_bfloat162*)&raw.z);
        float2 f3 = __bfloat1622float2(*(__nv_bfloat162*)&raw.w);
        a0 += w * f0.x; a1 += w * f0.y; a2 += w * f1.x; a3 += w * f1.y;
        a4 += w * f2.x; a5 += w * f2.y; a6 += w * f3.x; a7 += w * f3.y;
    }

    const float sc = ew[n * 4 + k] / (den + 1e-8f);
    float v0 = a0 * sc, v1 = a1 * sc, v2 = a2 * sc, v3 = a3 * sc;
    float v4 = a4 * sc, v5 = a5 * sc, v6 = a6 * sc, v7 = a7 * sc;

#pragma unroll
    for (int off = 8; off <= 16; off <<= 1) {
        v0 += __shfl_xor_sync(0xffffffffu, v0, off);
        v1 += __shfl_xor_sync(0xffffffffu, v1, off);
        v2 += __shfl_xor_sync(0xffffffffu, v2, off);
        v3 += __shfl_xor_sync(0xffffffffu, v3, off);
        v4 += __shfl_xor_sync(0xffffffffu, v4, off);
        v5 += __shfl_xor_sync(0xffffffffu, v5, off);
        v6 += __shfl_xor_sync(0xffffffffu, v6, off);
        v7 += __shfl_xor_sync(0xffffffffu, v7, off);
    }

    if (lane < 8) {
        const float4* xp = (const float4*)(x + n * 64 + lane * 8);
        float4 x0 = xp[0];
        float4 x1 = xp[1];
        float4* op = (float4*)(out + n * 64 + lane * 8);
        op[0] = make_float4(v0 + x0.x, v1 + x0.y, v2 + x0.z, v3 + x0.w);
        op[1] = make_float4(v4 + x1.x, v5 + x1.y, v6 + x1.z, v7 + x1.w);
    }
}

// ---------------- launch ----------------
extern "C" void kernel_launch(void* const* d_in, const int* in_sizes, int n_in,
                              void* d_out, int out_size) {
    const float* x   = (const float*)d_in[0];
    const int*   adj = (const int*)d_in[1];
    const float* ew  = (const float*)d_in[2];
    const float* W   = (const float*)d_in[3];
    const float* a   = (const float*)d_in[4];
    float*       out = (float*)d_out;

    const size_t smem = (64 * 256 + 64 * 68) * sizeof(float);  // 82944 B

    static cudaStream_t s2 = nullptr;
    static cudaEvent_t evF = nullptr, evJ = nullptr;
    if (!s2) {
        cudaFuncSetAttribute(k_gemm, cudaFuncAttributeMaxDynamicSharedMemorySize, (int)smem);
        cudaStreamCreateWithFlags(&s2, cudaStreamNonBlocking);
        cudaEventCreateWithFlags(&evF, cudaEventDisableTiming);
        cudaEventCreateWithFlags(&evJ, cudaEventDisableTiming);
    }

    // main stream: init -> gemm -> max ; side stream: cnt -> alloc -> scatter
    k_init<<<(NN + 255) / 256, 256>>>();
    cudaEventRecord(evF, 0);
    cudaStreamWaitEvent(s2, evF, 0);

    k_cnt<<<(EE + 255) / 256, 256, 0, s2>>>(adj);
    k_alloc<<<(NN + 255) / 256, 256, 0, s2>>>();
    k_scatter<<<(EE + 255) / 256, 256, 0, s2>>>(adj);
    cudaEventRecord(evJ, s2);

    k_gemm<<<(NN + 63) / 64, 256, smem>>>(x, W, a);
    k_max<<<(EE + 255) / 256, 256>>>(adj);

    cudaStreamWaitEvent(0, evJ, 0);
    k_gather<<<(NN * 32 + 255) / 256, 256>>>(x, ew, out);
}

// round 5
// speedup vs baseline: 3.4624x; 1.1878x over previous
#include <cuda_runtime.h>
#include <cuda_bf16.h>
#include <cstdint>

#define NN 50000
#define EE 850000
#define KH 4
#define DD 64
#define CC 256    // KH*DD
#define BSTRIDE 264

// ---------------- scratch ----------------
__device__ __nv_bfloat16 g_hb[(size_t)NN * CC];
__device__ float g_adst[NN * KH];
__device__ float g_asrc[NN * KH];
__device__ int   g_cnt[NN];
__device__ int   g_off[NN];
__device__ int   g_cur[NN];
__device__ int   g_csr[EE];
__device__ int   g_admax[KH];
__device__ int   g_asmax[KH];
__device__ int   g_total;

__device__ __forceinline__ int enc_f(float f) {
    int b = __float_as_int(f);
    return b >= 0 ? b : (b ^ 0x7fffffff);
}
__device__ __forceinline__ float dec_f(int v) {
    return v >= 0 ? __int_as_float(v) : __int_as_float(v ^ 0x7fffffff);
}
__device__ __forceinline__ unsigned f2tf32(float f) {
    unsigned r;
    asm("cvt.rna.tf32.f32 %0, %1;" : "=r"(r) : "f"(f));
    return r;
}
__device__ __forceinline__ void mma_tf32(float c[4], unsigned a0, unsigned a1,
                                         unsigned a2, unsigned a3,
                                         unsigned b0, unsigned b1) {
    asm volatile(
        "mma.sync.aligned.m16n8k8.row.col.f32.tf32.tf32.f32 "
        "{%0,%1,%2,%3}, {%4,%5,%6,%7}, {%8,%9}, {%0,%1,%2,%3};"
        : "+f"(c[0]), "+f"(c[1]), "+f"(c[2]), "+f"(c[3])
        : "r"(a0), "r"(a1), "r"(a2), "r"(a3), "r"(b0), "r"(b1));
}

// ---------------- K0: init ----------------
__global__ void k_init() {
    int t = blockIdx.x * blockDim.x + threadIdx.x;
    if (t < NN) g_cnt[t] = 0;
    if (t < KH) { g_admax[t] = (int)0x80000000; g_asmax[t] = (int)0x80000000; }
    if (t == KH) g_total = 0;
}

// ---------------- K1: tf32 MMA GEMM h = x@W + alpha dots, bf16 h out ----------------
// Block: 256 thr (8 warps), tile 64 nodes x 256 cols, K=64.
// warp wm = w&3 -> nodes [wm*16, wm*16+16);  wn = w>>2 -> cols [wn*128, wn*128+128)
__global__ __launch_bounds__(256, 2) void k_gemm(const float* __restrict__ x,
                                                 const float* __restrict__ W,
                                                 const float* __restrict__ a) {
    extern __shared__ unsigned sm_u[];
    unsigned* Bs = sm_u;                         // [64][264] tf32
    unsigned* Xs = sm_u + 64 * BSTRIDE;          // [64][68]  tf32
    float* ads = (float*)(Xs + 64 * 68);         // [256]
    float* ass = ads + 256;                      // [256]
    __nv_bfloat162* Cs = (__nv_bfloat162*)sm_u;  // [64][132] bf162 (reuses Bs after sync)

    const int t = threadIdx.x;
    {
        int k = t >> 6, o = t & 63;
        ads[t] = a[k * 128 + o];
        ass[t] = a[k * 128 + 64 + o];
    }
    for (int idx = t; idx < 64 * 256; idx += 256) {
        int d = idx >> 8, c = idx & 255;
        Bs[d * BSTRIDE + c] = f2tf32(W[(c >> 6) * 4096 + d * 64 + (c & 63)]);
    }
    const int node0 = blockIdx.x * 64;
    for (int idx = t; idx < 64 * 64; idx += 256) {
        int nl = idx >> 6, k = idx & 63;
        int n = node0 + nl;
        Xs[nl * 68 + k] = f2tf32((n < NN) ? x[n * 64 + k] : 0.f);
    }
    __syncthreads();

    const int w = t >> 5, lane = t & 31;
    const int wm = w & 3, wn = w >> 2;
    const int qr = lane >> 2, qc = lane & 3;

    float acc[16][4];
#pragma unroll
    for (int nt = 0; nt < 16; nt++)
#pragma unroll
        for (int j = 0; j < 4; j++) acc[nt][j] = 0.f;

#pragma unroll
    for (int kc = 0; kc < 8; kc++) {
        const int kb = kc * 8;
        const unsigned* Xp = Xs + (wm * 16 + qr) * 68 + kb + qc;
        unsigned a0 = Xp[0];
        unsigned a1 = Xp[8 * 68];
        unsigned a2 = Xp[4];
        unsigned a3 = Xp[8 * 68 + 4];
        const unsigned* Bp = Bs + (kb + qc) * BSTRIDE + wn * 128 + qr;
#pragma unroll
        for (int nt = 0; nt < 16; nt++) {
            unsigned b0 = Bp[nt * 8];
            unsigned b1 = Bp[4 * BSTRIDE + nt * 8];
            mma_tf32(acc[nt], a0, a1, a2, a3, b0, b1);
        }
    }

    // ---- alpha dots from C fragments (cols: wn*128 + nt*8 + qc*2 + {0,1}) ----
    float pd0[2] = {0.f, 0.f}, pd1[2] = {0.f, 0.f};  // [head-in-half] rows r0,r1
    float ps0[2] = {0.f, 0.f}, ps1[2] = {0.f, 0.f};
#pragma unroll
    for (int nt = 0; nt < 16; nt++) {
        int c = wn * 128 + nt * 8 + qc * 2;
        int hh = nt >> 3;
        float d0 = ads[c], d1 = ads[c + 1], s0 = ass[c], s1 = ass[c + 1];
        pd0[hh] += acc[nt][0] * d0 + acc[nt][1] * d1;
        pd1[hh] += acc[nt][2] * d0 + acc[nt][3] * d1;
        ps0[hh] += acc[nt][0] * s0 + acc[nt][1] * s1;
        ps1[hh] += acc[nt][2] * s0 + acc[nt][3] * s1;
    }
#pragma unroll
    for (int off = 1; off <= 2; off <<= 1) {
#pragma unroll
        for (int hh = 0; hh < 2; hh++) {
            pd0[hh] += __shfl_xor_sync(0xffffffffu, pd0[hh], off);
            pd1[hh] += __shfl_xor_sync(0xffffffffu, pd1[hh], off);
            ps0[hh] += __shfl_xor_sync(0xffffffffu, ps0[hh], off);
            ps1[hh] += __shfl_xor_sync(0xffffffffu, ps1[hh], off);
        }
    }
    if (qc == 0) {
        int n0 = node0 + wm * 16 + qr;
        int n1 = n0 + 8;
        if (n0 < NN) {
            g_adst[n0 * 4 + wn * 2 + 0] = pd0[0];
            g_adst[n0 * 4 + wn * 2 + 1] = pd0[1];
            g_asrc[n0 * 4 + wn * 2 + 0] = ps0[0];
            g_asrc[n0 * 4 + wn * 2 + 1] = ps0[1];
        }
        if (n1 < NN) {
            g_adst[n1 * 4 + wn * 2 + 0] = pd1[0];
            g_adst[n1 * 4 + wn * 2 + 1] = pd1[1];
            g_asrc[n1 * 4 + wn * 2 + 0] = ps1[0];
            g_asrc[n1 * 4 + wn * 2 + 1] = ps1[1];
        }
    }

    // ---- stage h as bf16 in smem (reuse Bs region), then coalesced global store ----
    __syncthreads();
#pragma unroll
    for (int nt = 0; nt < 16; nt++) {
        int col2 = (wn * 128 + nt * 8 + qc * 2) >> 1;  // bf162 index
        Cs[(wm * 16 + qr) * 132 + col2]     = __floats2bfloat162_rn(acc[nt][0], acc[nt][1]);
        Cs[(wm * 16 + qr + 8) * 132 + col2] = __floats2bfloat162_rn(acc[nt][2], acc[nt][3]);
    }
    __syncthreads();
    for (int idx = t; idx < 64 * 32; idx += 256) {
        int r = idx >> 5, cg = idx & 31;
        int n = node0 + r;
        if (n < NN)
            *(uint4*)(g_hb + (size_t)n * CC + cg * 8) =
                *(const uint4*)((const char*)Cs + r * 528 + cg * 16);
    }
}

// ---------------- K2a: degree count (side stream) --------------
__global__ void k_cnt(const int* __restrict__ adj) {
    int e = blockIdx.x * blockDim.x + threadIdx.x;
    if (e < EE) {
        int dst = adj[e];
        if ((unsigned)dst < NN) atomicAdd(&g_cnt[dst], 1);
    }
}

// ---------------- K2b: parallel bucket allocation (order-free) ----------------
__global__ void k_alloc() {
    const int n = blockIdx.x * blockDim.x + threadIdx.x;
    const int lane = threadIdx.x & 31;
    int c = (n < NN) ? g_cnt[n] : 0;
    int incl = c;
#pragma unroll
    for (int off = 1; off < 32; off <<= 1) {
        int v = __shfl_up_sync(0xffffffffu, incl, off);
        if (lane >= off) incl += v;
    }
    int wtotal = __shfl_sync(0xffffffffu, incl, 31);
    int base = 0;
    if (lane == 31) base = atomicAdd(&g_total, wtotal);
    base = __shfl_sync(0xffffffffu, base, 31);
    if (n < NN) {
        int off = base + incl - c;
        g_off[n] = off;
        g_cur[n] = off;
    }
}

// ---------------- K2c: scatter edges into CSR buckets (side stream) ----------------
__global__ void k_scatter(const int* __restrict__ adj) {
    int e = blockIdx.x * blockDim.x + threadIdx.x;
    if (e < EE) {
        int dst = adj[e];
        int src = adj[EE + e];
        if ((unsigned)dst < NN && (unsigned)src < NN) {
            int p = atomicAdd(&g_cur[dst], 1);
            if ((unsigned)p < EE) g_csr[p] = src;
        }
    }
}

// ---------------- K3: node-level per-head max of alphas (upper bound for softmax M) --
__global__ void k_nmax() {
    int n = blockIdx.x * blockDim.x + threadIdx.x;
    float4 ad = make_float4(-1e30f, -1e30f, -1e30f, -1e30f);
    float4 as = ad;
    if (n < NN) {
        ad = *(const float4*)&g_adst[n * 4];
        as = *(const float4*)&g_asrc[n * 4];
    }
#pragma unroll
    for (int off = 16; off; off >>= 1) {
        ad.x = fmaxf(ad.x, __shfl_xor_sync(0xffffffffu, ad.x, off));
        ad.y = fmaxf(ad.y, __shfl_xor_sync(0xffffffffu, ad.y, off));
        ad.z = fmaxf(ad.z, __shfl_xor_sync(0xffffffffu, ad.z, off));
        ad.w = fmaxf(ad.w, __shfl_xor_sync(0xffffffffu, ad.w, off));
        as.x = fmaxf(as.x, __shfl_xor_sync(0xffffffffu, as.x, off));
        as.y = fmaxf(as.y, __shfl_xor_sync(0xffffffffu, as.y, off));
        as.z = fmaxf(as.z, __shfl_xor_sync(0xffffffffu, as.z, off));
        as.w = fmaxf(as.w, __shfl_xor_sync(0xffffffffu, as.w, off));
    }
    if ((threadIdx.x & 31) == 0) {
        atomicMax(&g_admax[0], enc_f(ad.x));
        atomicMax(&g_admax[1], enc_f(ad.y));
        atomicMax(&g_admax[2], enc_f(ad.z));
        atomicMax(&g_admax[3], enc_f(ad.w));
        atomicMax(&g_asmax[0], enc_f(as.x));
        atomicMax(&g_asmax[1], enc_f(as.y));
        atomicMax(&g_asmax[2], enc_f(as.z));
        atomicMax(&g_asmax[3], enc_f(as.w));
    }
}

// ---------------- K4: gather + softmax aggregate + head mix + residual ----------------
__global__ __launch_bounds__(256) void k_gather(const float* __restrict__ x,
                                                const float* __restrict__ ew,
                                                float* __restrict__ out) {
    const int n = (blockIdx.x * blockDim.x + threadIdx.x) >> 5;
    const int lane = threadIdx.x & 31;
    if (n >= NN) return;
    const int k = lane >> 3;

    float M = dec_f(g_admax[k]) + dec_f(g_asmax[k]);  // upper bound of max logit pre-lrelu
    M = fmaxf(M, 0.01f * M);
    const float ad = g_adst[n * 4 + k];
    const int beg = g_off[n];
    const int deg = g_cnt[n];

    float a0 = 0.f, a1 = 0.f, a2 = 0.f, a3 = 0.f, a4 = 0.f, a5 = 0.f, a6 = 0.f, a7 = 0.f;
    float den = 0.f;

    const __nv_bfloat16* hbase = g_hb + lane * 8;
#pragma unroll 2
    for (int i = 0; i < deg; i++) {
        int src = g_csr[beg + i];
        float as = g_asrc[src * 4 + k];
        float s = ad + as;
        float l = fmaxf(s, 0.01f * s);
        float w = __expf(l - M);
        den += w;
        uint4 raw = *(const uint4*)(hbase + (size_t)src * CC);
        float2 f0 = __bfloat1622float2(*(__nv_bfloat162*)&raw.x);
        float2 f1 = __bfloat1622float2(*(__nv_bfloat162*)&raw.y);
        float2 f2 = __bfloat1622float2(*(__nv_bfloat162*)&raw.z);
        float2 f3 = __bfloat1622float2(*(__nv_bfloat162*)&raw.w);
        a0 += w * f0.x; a1 += w * f0.y; a2 += w * f1.x; a3 += w * f1.y;
        a4 += w * f2.x; a5 += w * f2.y; a6 += w * f3.x; a7 += w * f3.y;
    }

    const float sc = ew[n * 4 + k] / (den + 1e-8f);
    float v0 = a0 * sc, v1 = a1 * sc, v2 = a2 * sc, v3 = a3 * sc;
    float v4 = a4 * sc, v5 = a5 * sc, v6 = a6 * sc, v7 = a7 * sc;

#pragma unroll
    for (int off = 8; off <= 16; off <<= 1) {
        v0 += __shfl_xor_sync(0xffffffffu, v0, off);
        v1 += __shfl_xor_sync(0xffffffffu, v1, off);
        v2 += __shfl_xor_sync(0xffffffffu, v2, off);
        v3 += __shfl_xor_sync(0xffffffffu, v3, off);
        v4 += __shfl_xor_sync(0xffffffffu, v4, off);
        v5 += __shfl_xor_sync(0xffffffffu, v5, off);
        v6 += __shfl_xor_sync(0xffffffffu, v6, off);
        v7 += __shfl_xor_sync(0xffffffffu, v7, off);
    }

    if (lane < 8) {
        const float4* xp = (const float4*)(x + n * 64 + lane * 8);
        float4 x0 = xp[0];
        float4 x1 = xp[1];
        float4* op = (float4*)(out + n * 64 + lane * 8);
        op[0] = make_float4(v0 + x0.x, v1 + x0.y, v2 + x0.z, v3 + x0.w);
        op[1] = make_float4(v4 + x1.x, v5 + x1.y, v6 + x1.z, v7 + x1.w);
    }
}

// ---------------- launch ----------------
extern "C" void kernel_launch(void* const* d_in, const int* in_sizes, int n_in,
                              void* d_out, int out_size) {
    const float* x   = (const float*)d_in[0];
    const int*   adj = (const int*)d_in[1];
    const float* ew  = (const float*)d_in[2];
    const float* W   = (const float*)d_in[3];
    const float* a   = (const float*)d_in[4];
    float*       out = (float*)d_out;

    const size_t smem = (64 * BSTRIDE + 64 * 68) * sizeof(unsigned) + 512 * sizeof(float);

    static cudaStream_t s2 = nullptr;
    static cudaEvent_t evF = nullptr, evJ = nullptr;
    if (!s2) {
        cudaFuncSetAttribute(k_gemm, cudaFuncAttributeMaxDynamicSharedMemorySize, (int)smem);
        cudaStreamCreateWithFlags(&s2, cudaStreamNonBlocking);
        cudaEventCreateWithFlags(&evF, cudaEventDisableTiming);
        cudaEventCreateWithFlags(&evJ, cudaEventDisableTiming);
    }

    k_init<<<(NN + 255) / 256, 256>>>();
    cudaEventRecord(evF, 0);
    cudaStreamWaitEvent(s2, evF, 0);

    k_cnt<<<(EE + 255) / 256, 256, 0, s2>>>(adj);
    k_alloc<<<(NN + 255) / 256, 256, 0, s2>>>();
    k_scatter<<<(EE + 255) / 256, 256, 0, s2>>>(adj);
    cudaEventRecord(evJ, s2);

    k_gemm<<<(NN + 63) / 64, 256, smem>>>(x, W, a);
    k_nmax<<<(NN + 255) / 256, 256>>>();

    cudaStreamWaitEvent(0, evJ, 0);
    k_gather<<<(NN * 32 + 255) / 256, 256>>>(x, ew, out);
}

// round 6
// speedup vs baseline: 3.5976x; 1.0390x over previous
#include <cuda_runtime.h>
#include <cuda_bf16.h>
#include <cstdint>

#define NN 50000
#define EE 850000
#define KH 4
#define DD 64
#define CC 256    // KH*DD
#define BSTRIDE 264

// ---------------- scratch ----------------
__device__ __nv_bfloat16 g_hb[(size_t)NN * CC];
__device__ float g_adst[NN * KH];
__device__ float g_asrc[NN * KH];
__device__ int   g_cnt[NN];
__device__ int   g_off[NN];
__device__ int   g_cur[NN];
__device__ int   g_csr[EE];
__device__ int   g_admax[KH];
__device__ int   g_asmax[KH];
__device__ int   g_total;

__device__ __forceinline__ int enc_f(float f) {
    int b = __float_as_int(f);
    return b >= 0 ? b : (b ^ 0x7fffffff);
}
__device__ __forceinline__ float dec_f(int v) {
    return v >= 0 ? __int_as_float(v) : __int_as_float(v ^ 0x7fffffff);
}
__device__ __forceinline__ unsigned f2tf32(float f) {
    unsigned r;
    asm("cvt.rna.tf32.f32 %0, %1;" : "=r"(r) : "f"(f));
    return r;
}
__device__ __forceinline__ void mma_tf32(float c[4], unsigned a0, unsigned a1,
                                         unsigned a2, unsigned a3,
                                         unsigned b0, unsigned b1) {
    asm volatile(
        "mma.sync.aligned.m16n8k8.row.col.f32.tf32.tf32.f32 "
        "{%0,%1,%2,%3}, {%4,%5,%6,%7}, {%8,%9}, {%0,%1,%2,%3};"
        : "+f"(c[0]), "+f"(c[1]), "+f"(c[2]), "+f"(c[3])
        : "r"(a0), "r"(a1), "r"(a2), "r"(a3), "r"(b0), "r"(b1));
}

// ---------------- K0: init ----------------
__global__ void k_init() {
    int t = blockIdx.x * blockDim.x + threadIdx.x;
    if (t < NN) g_cnt[t] = 0;
    if (t < KH) { g_admax[t] = (int)0x80000000; g_asmax[t] = (int)0x80000000; }
    if (t == KH) g_total = 0;
}

// ---------------- K1: tf32 MMA GEMM h = x@W + alpha dots, bf16 h out ----------------
__global__ __launch_bounds__(256, 2) void k_gemm(const float* __restrict__ x,
                                                 const float* __restrict__ W,
                                                 const float* __restrict__ a) {
    extern __shared__ unsigned sm_u[];
    unsigned* Bs = sm_u;                         // [64][264] tf32
    unsigned* Xs = sm_u + 64 * BSTRIDE;          // [64][68]  tf32
    float* ads = (float*)(Xs + 64 * 68);         // [256]
    float* ass = ads + 256;                      // [256]
    __nv_bfloat162* Cs = (__nv_bfloat162*)sm_u;  // reuse Bs region after sync

    const int t = threadIdx.x;
    {
        int k = t >> 6, o = t & 63;
        ads[t] = a[k * 128 + o];
        ass[t] = a[k * 128 + 64 + o];
    }
    for (int idx = t; idx < 64 * 256; idx += 256) {
        int d = idx >> 8, c = idx & 255;
        Bs[d * BSTRIDE + c] = f2tf32(W[(c >> 6) * 4096 + d * 64 + (c & 63)]);
    }
    const int node0 = blockIdx.x * 64;
    for (int idx = t; idx < 64 * 64; idx += 256) {
        int nl = idx >> 6, k = idx & 63;
        int n = node0 + nl;
        Xs[nl * 68 + k] = f2tf32((n < NN) ? x[n * 64 + k] : 0.f);
    }
    __syncthreads();

    const int w = t >> 5, lane = t & 31;
    const int wm = w & 3, wn = w >> 2;
    const int qr = lane >> 2, qc = lane & 3;

    float acc[16][4];
#pragma unroll
    for (int nt = 0; nt < 16; nt++)
#pragma unroll
        for (int j = 0; j < 4; j++) acc[nt][j] = 0.f;

#pragma unroll
    for (int kc = 0; kc < 8; kc++) {
        const int kb = kc * 8;
        const unsigned* Xp = Xs + (wm * 16 + qr) * 68 + kb + qc;
        unsigned a0 = Xp[0];
        unsigned a1 = Xp[8 * 68];
        unsigned a2 = Xp[4];
        unsigned a3 = Xp[8 * 68 + 4];
        const unsigned* Bp = Bs + (kb + qc) * BSTRIDE + wn * 128 + qr;
#pragma unroll
        for (int nt = 0; nt < 16; nt++) {
            unsigned b0 = Bp[nt * 8];
            unsigned b1 = Bp[4 * BSTRIDE + nt * 8];
            mma_tf32(acc[nt], a0, a1, a2, a3, b0, b1);
        }
    }

    // ---- alpha dots from C fragments ----
    float pd0[2] = {0.f, 0.f}, pd1[2] = {0.f, 0.f};
    float ps0[2] = {0.f, 0.f}, ps1[2] = {0.f, 0.f};
#pragma unroll
    for (int nt = 0; nt < 16; nt++) {
        int c = wn * 128 + nt * 8 + qc * 2;
        int hh = nt >> 3;
        float d0 = ads[c], d1 = ads[c + 1], s0 = ass[c], s1 = ass[c + 1];
        pd0[hh] += acc[nt][0] * d0 + acc[nt][1] * d1;
        pd1[hh] += acc[nt][2] * d0 + acc[nt][3] * d1;
        ps0[hh] += acc[nt][0] * s0 + acc[nt][1] * s1;
        ps1[hh] += acc[nt][2] * s0 + acc[nt][3] * s1;
    }
#pragma unroll
    for (int off = 1; off <= 2; off <<= 1) {
#pragma unroll
        for (int hh = 0; hh < 2; hh++) {
            pd0[hh] += __shfl_xor_sync(0xffffffffu, pd0[hh], off);
            pd1[hh] += __shfl_xor_sync(0xffffffffu, pd1[hh], off);
            ps0[hh] += __shfl_xor_sync(0xffffffffu, ps0[hh], off);
            ps1[hh] += __shfl_xor_sync(0xffffffffu, ps1[hh], off);
        }
    }
    if (qc == 0) {
        int n0 = node0 + wm * 16 + qr;
        int n1 = n0 + 8;
        if (n0 < NN) {
            g_adst[n0 * 4 + wn * 2 + 0] = pd0[0];
            g_adst[n0 * 4 + wn * 2 + 1] = pd0[1];
            g_asrc[n0 * 4 + wn * 2 + 0] = ps0[0];
            g_asrc[n0 * 4 + wn * 2 + 1] = ps0[1];
        }
        if (n1 < NN) {
            g_adst[n1 * 4 + wn * 2 + 0] = pd1[0];
            g_adst[n1 * 4 + wn * 2 + 1] = pd1[1];
            g_asrc[n1 * 4 + wn * 2 + 0] = ps1[0];
            g_asrc[n1 * 4 + wn * 2 + 1] = ps1[1];
        }
    }

    // ---- stage bf16 h in smem, coalesced global store ----
    __syncthreads();
#pragma unroll
    for (int nt = 0; nt < 16; nt++) {
        int col2 = (wn * 128 + nt * 8 + qc * 2) >> 1;
        Cs[(wm * 16 + qr) * 132 + col2]     = __floats2bfloat162_rn(acc[nt][0], acc[nt][1]);
        Cs[(wm * 16 + qr + 8) * 132 + col2] = __floats2bfloat162_rn(acc[nt][2], acc[nt][3]);
    }
    __syncthreads();
    for (int idx = t; idx < 64 * 32; idx += 256) {
        int r = idx >> 5, cg = idx & 31;
        int n = node0 + r;
        if (n < NN)
            *(uint4*)(g_hb + (size_t)n * CC + cg * 8) =
                *(const uint4*)((const char*)Cs + r * 528 + cg * 16);
    }
}

// ---------------- K2a: degree count, 4 edges/thread (side stream) --------------
__global__ void k_cnt(const int* __restrict__ adj) {
    int e4 = (blockIdx.x * blockDim.x + threadIdx.x) * 4;
    if (e4 + 3 < EE) {
        int4 d = *(const int4*)(adj + e4);
        if ((unsigned)d.x < NN) atomicAdd(&g_cnt[d.x], 1);
        if ((unsigned)d.y < NN) atomicAdd(&g_cnt[d.y], 1);
        if ((unsigned)d.z < NN) atomicAdd(&g_cnt[d.z], 1);
        if ((unsigned)d.w < NN) atomicAdd(&g_cnt[d.w], 1);
    } else {
        for (int e = e4; e < EE; e++) {
            int dst = adj[e];
            if ((unsigned)dst < NN) atomicAdd(&g_cnt[dst], 1);
        }
    }
}

// ---------------- K2b: parallel bucket allocation ----------------
__global__ void k_alloc() {
    const int n = blockIdx.x * blockDim.x + threadIdx.x;
    const int lane = threadIdx.x & 31;
    int c = (n < NN) ? g_cnt[n] : 0;
    int incl = c;
#pragma unroll
    for (int off = 1; off < 32; off <<= 1) {
        int v = __shfl_up_sync(0xffffffffu, incl, off);
        if (lane >= off) incl += v;
    }
    int wtotal = __shfl_sync(0xffffffffu, incl, 31);
    int base = 0;
    if (lane == 31) base = atomicAdd(&g_total, wtotal);
    base = __shfl_sync(0xffffffffu, base, 31);
    if (n < NN) {
        int off = base + incl - c;
        g_off[n] = off;
        g_cur[n] = off;
    }
}

// ---------------- K2c: scatter, 4 edges/thread (side stream) ----------------
__global__ void k_scatter(const int* __restrict__ adj) {
    int e4 = (blockIdx.x * blockDim.x + threadIdx.x) * 4;
    if (e4 + 3 < EE) {
        int4 d = *(const int4*)(adj + e4);
        int4 s = *(const int4*)(adj + EE + e4);
        int p0 = ((unsigned)d.x < NN) ? atomicAdd(&g_cur[d.x], 1) : -1;
        int p1 = ((unsigned)d.y < NN) ? atomicAdd(&g_cur[d.y], 1) : -1;
        int p2 = ((unsigned)d.z < NN) ? atomicAdd(&g_cur[d.z], 1) : -1;
        int p3 = ((unsigned)d.w < NN) ? atomicAdd(&g_cur[d.w], 1) : -1;
        if ((unsigned)p0 < EE) g_csr[p0] = s.x;
        if ((unsigned)p1 < EE) g_csr[p1] = s.y;
        if ((unsigned)p2 < EE) g_csr[p2] = s.z;
        if ((unsigned)p3 < EE) g_csr[p3] = s.w;
    } else {
        for (int e = e4; e < EE; e++) {
            int dst = adj[e];
            int src = adj[EE + e];
            if ((unsigned)dst < NN && (unsigned)src < NN) {
                int p = atomicAdd(&g_cur[dst], 1);
                if ((unsigned)p < EE) g_csr[p] = src;
            }
        }
    }
}

// ---------------- K3: node-level per-head max of alphas ----------------
__global__ void k_nmax() {
    int n = blockIdx.x * blockDim.x + threadIdx.x;
    float4 ad = make_float4(-1e30f, -1e30f, -1e30f, -1e30f);
    float4 as = ad;
    if (n < NN) {
        ad = *(const float4*)&g_adst[n * 4];
        as = *(const float4*)&g_asrc[n * 4];
    }
#pragma unroll
    for (int off = 16; off; off >>= 1) {
        ad.x = fmaxf(ad.x, __shfl_xor_sync(0xffffffffu, ad.x, off));
        ad.y = fmaxf(ad.y, __shfl_xor_sync(0xffffffffu, ad.y, off));
        ad.z = fmaxf(ad.z, __shfl_xor_sync(0xffffffffu, ad.z, off));
        ad.w = fmaxf(ad.w, __shfl_xor_sync(0xffffffffu, ad.w, off));
        as.x = fmaxf(as.x, __shfl_xor_sync(0xffffffffu, as.x, off));
        as.y = fmaxf(as.y, __shfl_xor_sync(0xffffffffu, as.y, off));
        as.z = fmaxf(as.z, __shfl_xor_sync(0xffffffffu, as.z, off));
        as.w = fmaxf(as.w, __shfl_xor_sync(0xffffffffu, as.w, off));
    }
    if ((threadIdx.x & 31) == 0) {
        atomicMax(&g_admax[0], enc_f(ad.x));
        atomicMax(&g_admax[1], enc_f(ad.y));
        atomicMax(&g_admax[2], enc_f(ad.z));
        atomicMax(&g_admax[3], enc_f(ad.w));
        atomicMax(&g_asmax[0], enc_f(as.x));
        atomicMax(&g_asmax[1], enc_f(as.y));
        atomicMax(&g_asmax[2], enc_f(as.z));
        atomicMax(&g_asmax[3], enc_f(as.w));
    }
}

// ---------------- K4: gather, 4-edge batched for MLP ----------------
__global__ __launch_bounds__(256) void k_gather(const float* __restrict__ x,
                                                const float* __restrict__ ew,
                                                float* __restrict__ out) {
    const int n = (blockIdx.x * blockDim.x + threadIdx.x) >> 5;
    const int lane = threadIdx.x & 31;
    if (n >= NN) return;
    const int k = lane >> 3;

    float M = dec_f(g_admax[k]) + dec_f(g_asmax[k]);
    M = fmaxf(M, 0.01f * M);
    const float ad = g_adst[n * 4 + k];
    const int beg = g_off[n];
    const int end = beg + g_cnt[n];

    float a0 = 0.f, a1 = 0.f, a2 = 0.f, a3 = 0.f, a4 = 0.f, a5 = 0.f, a6 = 0.f, a7 = 0.f;
    float den = 0.f;

    const __nv_bfloat16* hbase = g_hb + lane * 8;
    int i = beg;
    for (; i + 4 <= end; i += 4) {
        // batch the index loads (independent, broadcast within warp)
        int s0 = g_csr[i], s1 = g_csr[i + 1], s2 = g_csr[i + 2], s3 = g_csr[i + 3];
        // 4 independent alpha loads + 4 independent 16B h loads in flight
        float as0 = g_asrc[s0 * 4 + k];
        float as1 = g_asrc[s1 * 4 + k];
        float as2 = g_asrc[s2 * 4 + k];
        float as3 = g_asrc[s3 * 4 + k];
        uint4 r0 = *(const uint4*)(hbase + (size_t)s0 * CC);
        uint4 r1 = *(const uint4*)(hbase + (size_t)s1 * CC);
        uint4 r2 = *(const uint4*)(hbase + (size_t)s2 * CC);
        uint4 r3 = *(const uint4*)(hbase + (size_t)s3 * CC);

        float t0 = ad + as0, t1 = ad + as1, t2 = ad + as2, t3 = ad + as3;
        float w0 = __expf(fmaxf(t0, 0.01f * t0) - M);
        float w1 = __expf(fmaxf(t1, 0.01f * t1) - M);
        float w2 = __expf(fmaxf(t2, 0.01f * t2) - M);
        float w3 = __expf(fmaxf(t3, 0.01f * t3) - M);
        den += (w0 + w1) + (w2 + w3);

        float2 f;
        f = __bfloat1622float2(*(__nv_bfloat162*)&r0.x); a0 += w0 * f.x; a1 += w0 * f.y;
        f = __bfloat1622float2(*(__nv_bfloat162*)&r0.y); a2 += w0 * f.x; a3 += w0 * f.y;
        f = __bfloat1622float2(*(__nv_bfloat162*)&r0.z); a4 += w0 * f.x; a5 += w0 * f.y;
        f = __bfloat1622float2(*(__nv_bfloat162*)&r0.w); a6 += w0 * f.x; a7 += w0 * f.y;
        f = __bfloat1622float2(*(__nv_bfloat162*)&r1.x); a0 += w1 * f.x; a1 += w1 * f.y;
        f = __bfloat1622float2(*(__nv_bfloat162*)&r1.y); a2 += w1 * f.x; a3 += w1 * f.y;
        f = __bfloat1622float2(*(__nv_bfloat162*)&r1.z); a4 += w1 * f.x; a5 += w1 * f.y;
        f = __bfloat1622float2(*(__nv_bfloat162*)&r1.w); a6 += w1 * f.x; a7 += w1 * f.y;
        f = __bfloat1622float2(*(__nv_bfloat162*)&r2.x); a0 += w2 * f.x; a1 += w2 * f.y;
        f = __bfloat1622float2(*(__nv_bfloat162*)&r2.y); a2 += w2 * f.x; a3 += w2 * f.y;
        f = __bfloat1622float2(*(__nv_bfloat162*)&r2.z); a4 += w2 * f.x; a5 += w2 * f.y;
        f = __bfloat1622float2(*(__nv_bfloat162*)&r2.w); a6 += w2 * f.x; a7 += w2 * f.y;
        f = __bfloat1622float2(*(__nv_bfloat162*)&r3.x); a0 += w3 * f.x; a1 += w3 * f.y;
        f = __bfloat1622float2(*(__nv_bfloat162*)&r3.y); a2 += w3 * f.x; a3 += w3 * f.y;
        f = __bfloat1622float2(*(__nv_bfloat162*)&r3.z); a4 += w3 * f.x; a5 += w3 * f.y;
        f = __bfloat1622float2(*(__nv_bfloat162*)&r3.w); a6 += w3 * f.x; a7 += w3 * f.y;
    }
    for (; i < end; i++) {
        int src = g_csr[i];
        float as = g_asrc[src * 4 + k];
        float s = ad + as;
        float w = __expf(fmaxf(s, 0.01f * s) - M);
        den += w;
        uint4 raw = *(const uint4*)(hbase + (size_t)src * CC);
        float2 f;
        f = __bfloat1622float2(*(__nv_bfloat162*)&raw.x); a0 += w * f.x; a1 += w * f.y;
        f = __bfloat1622float2(*(__nv_bfloat162*)&raw.y); a2 += w * f.x; a3 += w * f.y;
        f = __bfloat1622float2(*(__nv_bfloat162*)&raw.z); a4 += w * f.x; a5 += w * f.y;
        f = __bfloat1622float2(*(__nv_bfloat162*)&raw.w); a6 += w * f.x; a7 += w * f.y;
    }

    const float sc = ew[n * 4 + k] / (den + 1e-8f);
    float v0 = a0 * sc, v1 = a1 * sc, v2 = a2 * sc, v3 = a3 * sc;
    float v4 = a4 * sc, v5 = a5 * sc, v6 = a6 * sc, v7 = a7 * sc;

#pragma unroll
    for (int off = 8; off <= 16; off <<= 1) {
        v0 += __shfl_xor_sync(0xffffffffu, v0, off);
        v1 += __shfl_xor_sync(0xffffffffu, v1, off);
        v2 += __shfl_xor_sync(0xffffffffu, v2, off);
        v3 += __shfl_xor_sync(0xffffffffu, v3, off);
        v4 += __shfl_xor_sync(0xffffffffu, v4, off);
        v5 += __shfl_xor_sync(0xffffffffu, v5, off);
        v6 += __shfl_xor_sync(0xffffffffu, v6, off);
        v7 += __shfl_xor_sync(0xffffffffu, v7, off);
    }

    if (lane < 8) {
        const float4* xp = (const float4*)(x + n * 64 + lane * 8);
        float4 x0 = xp[0];
        float4 x1 = xp[1];
        float4* op = (float4*)(out + n * 64 + lane * 8);
        op[0] = make_float4(v0 + x0.x, v1 + x0.y, v2 + x0.z, v3 + x0.w);
        op[1] = make_float4(v4 + x1.x, v5 + x1.y, v6 + x1.z, v7 + x1.w);
    }
}

// ---------------- launch ----------------
extern "C" void kernel_launch(void* const* d_in, const int* in_sizes, int n_in,
                              void* d_out, int out_size) {
    const float* x   = (const float*)d_in[0];
    const int*   adj = (const int*)d_in[1];
    const float* ew  = (const float*)d_in[2];
    const float* W   = (const float*)d_in[3];
    const float* a   = (const float*)d_in[4];
    float*       out = (float*)d_out;

    const size_t smem = (64 * BSTRIDE + 64 * 68) * sizeof(unsigned) + 512 * sizeof(float);

    static cudaStream_t s2 = nullptr;
    static cudaEvent_t evF = nullptr, evJ = nullptr;
    if (!s2) {
        cudaFuncSetAttribute(k_gemm, cudaFuncAttributeMaxDynamicSharedMemorySize, (int)smem);
        cudaStreamCreateWithFlags(&s2, cudaStreamNonBlocking);
        cudaEventCreateWithFlags(&evF, cudaEventDisableTiming);
        cudaEventCreateWithFlags(&evJ, cudaEventDisableTiming);
    }

    k_init<<<(NN + 255) / 256, 256>>>();
    cudaEventRecord(evF, 0);
    cudaStreamWaitEvent(s2, evF, 0);

    const int E4 = (EE / 4 + 255) / 256;
    k_cnt<<<E4, 256, 0, s2>>>(adj);
    k_alloc<<<(NN + 255) / 256, 256, 0, s2>>>();
    k_scatter<<<E4, 256, 0, s2>>>(adj);
    cudaEventRecord(evJ, s2);

    k_gemm<<<(NN + 63) / 64, 256, smem>>>(x, W, a);
    k_nmax<<<(NN + 255) / 256, 256>>>();

    cudaStreamWaitEvent(0, evJ, 0);
    k_gather<<<(NN * 32 + 255) / 256, 256>>>(x, ew, out);
}